// round 17
// baseline (speedup 1.0000x reference)
#include <cuda_runtime.h>
#include <cuda_fp16.h>
#include <math.h>
#include <stdint.h>

// ---------------------------------------------------------------------------
// SiglipEncoderLayer  B=8 S=1024 E=768 H=12 D=64 I=3072  fp32 in/out
// R17: R16 + BN templated GEMM. N=768 GEMMs (O-proj, MLP-down) use 128x64
//      blocks to fix wave quantization (384 blocks / 296 concurrent = 1.3
//      waves -> 2). QKV / MLP-up stay 128x128. Numerics unchanged.
// ---------------------------------------------------------------------------

#define BB   8
#define SS   1024
#define EE   768
#define HH   12
#define DD   64
#define II   3072
#define MR   (BB*SS)            // 8192
#define NQKV (3*EE)             // 2304
#define EPSF 1e-6f
#define SCALE_F 0.125f

// ---- scratch (device globals, 128B aligned) -------------------------------
__device__ __align__(128) float g_x [MR*EE];
__device__ __align__(128) float g_bqkv[NQKV];

__device__ __align__(128) __half g_h1 [(size_t)MR*EE];
__device__ __align__(128) __half g_h2 [(size_t)MR*EE];
__device__ __align__(128) __half g_qkv[(size_t)MR*NQKV];
__device__ __align__(128) __half g_o  [(size_t)MR*EE];
__device__ __align__(128) __half g_m  [(size_t)MR*II];

__device__ __align__(128) __half g_wqkv[(size_t)NQKV*EE];
__device__ __align__(128) __half g_wo [(size_t)EE*EE];
__device__ __align__(128) __half g_w1 [(size_t)II*EE];
__device__ __align__(128) __half g_w2 [(size_t)EE*II];

// ---------------------------------------------------------------------------
__device__ __forceinline__ uint32_t smem_u32(const void* p) {
    uint32_t a;
    asm("{ .reg .u64 t; cvta.to.shared.u64 t, %1; cvt.u32.u64 %0, t; }"
        : "=r"(a) : "l"(p));
    return a;
}
__device__ __forceinline__ void cp_async16(uint32_t s, const void* g) {
    asm volatile("cp.async.cg.shared.global [%0], [%1], 16;" :: "r"(s), "l"(g) : "memory");
}
#define CP_COMMIT() asm volatile("cp.async.commit_group;" ::: "memory")
#define CP_WAIT(n)  asm volatile("cp.async.wait_group %0;" :: "n"(n) : "memory")

__device__ __forceinline__ void ldsm4(uint32_t* r, uint32_t addr) {
    asm volatile("ldmatrix.sync.aligned.m8n8.x4.shared.b16 {%0,%1,%2,%3}, [%4];"
        : "=r"(r[0]), "=r"(r[1]), "=r"(r[2]), "=r"(r[3]) : "r"(addr));
}
__device__ __forceinline__ void ldsm4t(uint32_t* r, uint32_t addr) {
    asm volatile("ldmatrix.sync.aligned.m8n8.x4.trans.shared.b16 {%0,%1,%2,%3}, [%4];"
        : "=r"(r[0]), "=r"(r[1]), "=r"(r[2]), "=r"(r[3]) : "r"(addr));
}
__device__ __forceinline__ void mma16816(float* d, const uint32_t* a, const uint32_t* b) {
    asm volatile(
        "mma.sync.aligned.m16n8k16.row.col.f32.f16.f16.f32 "
        "{%0,%1,%2,%3}, {%4,%5,%6,%7}, {%8,%9}, {%0,%1,%2,%3};"
        : "+f"(d[0]), "+f"(d[1]), "+f"(d[2]), "+f"(d[3])
        : "r"(a[0]), "r"(a[1]), "r"(a[2]), "r"(a[3]), "r"(b[0]), "r"(b[1]));
}
__device__ __forceinline__ float gelu_tanh(float x) {
    float x3 = x * x * x;
    float t  = tanhf(0.7978845608028654f * (x + 0.044715f * x3));
    return 0.5f * x * (1.0f + t);
}
__device__ __forceinline__ uint32_t pack2h(float x, float y) {
    __half2 H = __halves2half2(__float2half_rn(x), __float2half_rn(y));
    return *reinterpret_cast<uint32_t*>(&H);
}

// ---------------------------------------------------------------------------
// mma.sync GEMM (fp16), 4-stage cp.async ring, ONE barrier per iter,
// templated block width BN (128 or 64). Warp layout 4m x 2n; warp n-extent
// WN = BN/2.
//   MODE 0: opk plain = acc + bias                       (QKV-proj)
//   MODE 1: opk plain = gelu(acc + bias)                 (MLP up)
//   MODE 2: outf fp32 = acc + bias + res                 (O-proj, MLP down)
// ---------------------------------------------------------------------------
#define GEMM_NS 4

template<int MODE, int BN>
__global__ __launch_bounds__(256, 2)
void mma_gemm(const __half* __restrict__ A,
              const __half* __restrict__ W,
              const float* __restrict__ bias, const float* __restrict__ res,
              float* __restrict__ outf, __half* __restrict__ opk,
              int M, int N, int KP, int lda, int ldw, int ldo) {
    extern __shared__ __align__(128) char smbuf[];

    constexpr int WN  = BN / 2;          // warp n-extent
    constexpr int NF  = WN / 8;          // 8-wide n fragments per warp
    constexpr int STG = 8192 + BN * 64;  // A 8KB + B tile bytes
    constexpr int NCH = (512 + BN * 4) / 256;  // 16B chunks per thread per stage

    const int tid  = threadIdx.x;
    const int wid  = tid >> 5;
    const int lane = tid & 31;
    const int wm   = wid & 3;
    const int wn   = wid >> 2;
    const int m0   = blockIdx.y * 128;
    const int n0   = blockIdx.x * BN;

    const uint32_t sb = smem_u32(smbuf);

    float acc[2][NF][4];
    #pragma unroll
    for (int mf = 0; mf < 2; mf++)
        #pragma unroll
        for (int nf = 0; nf < NF; nf++)
            #pragma unroll
            for (int r = 0; r < 4; r++) acc[mf][nf][r] = 0.f;

    const int nc = KP >> 5;

    auto loadc = [&](int c, int s) {
        const int k0 = c << 5;
        uint32_t as = sb + (uint32_t)s * STG;
        uint32_t bs = as + 8192u;
        #pragma unroll
        for (int i = 0; i < NCH; i++) {
            int cid = tid + i * 256;
            if (cid < 512) {
                int row = cid >> 2, ch = cid & 3;
                uint32_t soff = row * 64u + ((uint32_t)(ch ^ (row & 3)) << 4);
                cp_async16(as + soff, A + (size_t)(m0 + row) * lda + k0 + ch * 8);
            } else {
                int c2 = cid - 512;
                int row = c2 >> 2, ch = c2 & 3;
                uint32_t soff = row * 64u + ((uint32_t)(ch ^ (row & 3)) << 4);
                cp_async16(bs + soff, W + (size_t)(n0 + row) * ldw + k0 + ch * 8);
            }
        }
    };

    #pragma unroll
    for (int p = 0; p < GEMM_NS - 1; p++) { loadc(p, p); CP_COMMIT(); }

    for (int c = 0; c < nc; c++) {
        CP_WAIT(GEMM_NS - 2);
        __syncthreads();

        // issue next stage now (overlaps mma); slot (c+3)&3 was last read in
        // iter c-1, protected by the barrier above.
        const int nxt = c + GEMM_NS - 1;
        if (nxt < nc) loadc(nxt, nxt & (GEMM_NS - 1));
        CP_COMMIT();

        const uint32_t as = sb + (uint32_t)(c & (GEMM_NS - 1)) * STG;
        const uint32_t bs = as + 8192u;
        const int j = lane >> 3, r = lane & 7;

        #pragma unroll
        for (int ks = 0; ks < 2; ks++) {
            uint32_t af[2][4];
            #pragma unroll
            for (int mf = 0; mf < 2; mf++) {
                int row = wm * 32 + mf * 16 + (j & 1) * 8 + r;
                int kc  = ks * 2 + (j >> 1);
                ldsm4(af[mf], as + row * 64u + ((uint32_t)(kc ^ (row & 3)) << 4));
            }
            uint32_t bf[NF][2];
            #pragma unroll
            for (int tp = 0; tp < NF / 2; tp++) {
                int nrow = wn * WN + tp * 16 + (j >> 1) * 8 + r;
                int kc   = ks * 2 + (j & 1);
                uint32_t t4[4];
                ldsm4(t4, bs + nrow * 64u + ((uint32_t)(kc ^ (nrow & 3)) << 4));
                bf[2*tp][0]   = t4[0]; bf[2*tp][1]   = t4[1];
                bf[2*tp+1][0] = t4[2]; bf[2*tp+1][1] = t4[3];
            }
            #pragma unroll
            for (int mf = 0; mf < 2; mf++)
                #pragma unroll
                for (int nf = 0; nf < NF; nf++)
                    mma16816(acc[mf][nf], af[mf], bf[nf]);
        }
        // no trailing barrier: next iter's barrier provides ordering
    }

    const int gi = lane >> 2, ci = lane & 3;
    #pragma unroll
    for (int mf = 0; mf < 2; mf++) {
        int r0 = m0 + wm * 32 + mf * 16 + gi;
        #pragma unroll
        for (int nf = 0; nf < NF; nf++) {
            int col = n0 + wn * WN + nf * 8 + ci * 2;
            float b0 = bias[col], b1 = bias[col + 1];
            float v00 = acc[mf][nf][0] + b0, v01 = acc[mf][nf][1] + b1;
            float v10 = acc[mf][nf][2] + b0, v11 = acc[mf][nf][3] + b1;
            if (MODE == 0 || MODE == 1) {
                if (MODE == 1) {
                    v00 = gelu_tanh(v00); v01 = gelu_tanh(v01);
                    v10 = gelu_tanh(v10); v11 = gelu_tanh(v11);
                }
                *reinterpret_cast<__half2*>(opk + (size_t)r0 * ldo + col) =
                    __halves2half2(__float2half_rn(v00), __float2half_rn(v01));
                *reinterpret_cast<__half2*>(opk + (size_t)(r0 + 8) * ldo + col) =
                    __halves2half2(__float2half_rn(v10), __float2half_rn(v11));
            } else {
                const float2 r00 = *reinterpret_cast<const float2*>(res + (size_t)r0 * N + col);
                const float2 r10 = *reinterpret_cast<const float2*>(res + (size_t)(r0 + 8) * N + col);
                v00 += r00.x; v01 += r00.y; v10 += r10.x; v11 += r10.y;
                *reinterpret_cast<float2*>(outf + (size_t)r0 * N + col)       = make_float2(v00, v01);
                *reinterpret_cast<float2*>(outf + (size_t)(r0 + 8) * N + col) = make_float2(v10, v11);
            }
        }
    }
}

#define GEMM_SMEM_128 (GEMM_NS * (8192 + 128*64))   // 64 KB
#define GEMM_SMEM_64  (GEMM_NS * (8192 + 64*64))    // 48 KB

// ---------------------------------------------------------------------------
// Fused flash attention (plain fp16 1-pass), 3-stage KV ring, one barrier/iter.
// ---------------------------------------------------------------------------
#define FA_STG  32768                   // K,V = 2 x 16KB
#define FA_NS   3
#define FA_SMEM (16384 + FA_NS*FA_STG)  // Q + 3 stages = 112 KB

__global__ __launch_bounds__(256, 1)
void flash_attn(const __half* __restrict__ QKV,
                const float* __restrict__ mask,
                __half* __restrict__ Op) {
    extern __shared__ __align__(128) char fsm[];
    const uint32_t sb = smem_u32(fsm);
    const int tid = threadIdx.x, wid = tid >> 5, lane = tid & 31;
    const int qt = blockIdx.x, bh = blockIdx.y;
    const int b = bh / HH, h = bh - b * HH;
    const int q0 = qt * 128;
    const int j = lane >> 3, r = lane & 7;
    const int gi = lane >> 2, ci = lane & 3;

    const int qoff = h * DD;
    const int koff = EE + h * DD;
    const int voff = 2 * EE + h * DD;

    const uint32_t sQ   = sb;
    const uint32_t stg0 = sb + 16384u;

    {
        const size_t rbase = (size_t)(b * SS + q0);
        #pragma unroll
        for (int i = 0; i < 4; i++) {
            int idx = tid + i * 256;
            int row = idx >> 3, ch = idx & 7;
            uint32_t d = row * 128u + ((uint32_t)(ch ^ (row & 7)) << 4);
            cp_async16(sQ + d, QKV + (rbase + row) * NQKV + qoff + ch * 8);
        }
    }
    auto loadKV = [&](int it, int st) {
        const size_t rbase = (size_t)(b * SS + it * 128);
        uint32_t base = stg0 + (uint32_t)st * FA_STG;
        #pragma unroll
        for (int i = 0; i < 4; i++) {
            int idx = tid + i * 256;
            int row = idx >> 3, ch = idx & 7;
            const __half* g = QKV + (rbase + row) * NQKV + ch * 8;
            uint32_t d = base + row * 128u + ((uint32_t)(ch ^ (row & 7)) << 4);
            cp_async16(d,          g + koff);    // K
            cp_async16(d + 16384u, g + voff);    // V
        }
    };

    loadKV(0, 0);
    CP_COMMIT();
    loadKV(1, 1);
    CP_COMMIT();

    float m0v = -1e30f, m1v = -1e30f, l0 = 0.f, l1 = 0.f;
    float o[8][4];
    #pragma unroll
    for (int nt = 0; nt < 8; nt++)
        #pragma unroll
        for (int t = 0; t < 4; t++) o[nt][t] = 0.f;

    const int NIT = SS / 128;       // 8
    for (int it = 0; it < NIT; it++) {
        CP_WAIT(1);                 // group `it` complete (Q rides with group 0)
        __syncthreads();

        if (it + 2 < NIT) loadKV(it + 2, (it + 2) % FA_NS);
        CP_COMMIT();

        const uint32_t kb = stg0 + (uint32_t)(it % FA_NS) * FA_STG;

        float s[16][4];
        #pragma unroll
        for (int t = 0; t < 16; t++)
            #pragma unroll
            for (int u = 0; u < 4; u++) s[t][u] = 0.f;

        #pragma unroll
        for (int kc = 0; kc < 4; kc++) {
            uint32_t af[4];
            int arow = wid * 16 + (j & 1) * 8 + r;
            int ach  = kc * 2 + (j >> 1);
            ldsm4(af, sQ + arow * 128u + ((uint32_t)(ach ^ (arow & 7)) << 4));
            #pragma unroll
            for (int nt2 = 0; nt2 < 8; nt2++) {
                int brow = nt2 * 16 + (j >> 1) * 8 + r;
                int bch  = kc * 2 + (j & 1);
                uint32_t t4[4];
                ldsm4(t4, kb + brow * 128u + ((uint32_t)(bch ^ (brow & 7)) << 4));
                uint32_t b0[2] = {t4[0], t4[1]}, b1[2] = {t4[2], t4[3]};
                mma16816(s[2*nt2],   af, b0);
                mma16816(s[2*nt2+1], af, b1);
            }
        }

        const float* mr0 = mask + ((size_t)b * SS + (q0 + wid * 16 + gi)) * SS + it * 128;
        const float* mr1 = mr0 + 8 * (size_t)SS;
        float mx0 = -1e30f, mx1 = -1e30f;
        #pragma unroll
        for (int t = 0; t < 16; t++) {
            float2 u0 = *reinterpret_cast<const float2*>(mr0 + t * 8 + ci * 2);
            float2 u1 = *reinterpret_cast<const float2*>(mr1 + t * 8 + ci * 2);
            s[t][0] = s[t][0] * SCALE_F + u0.x;
            s[t][1] = s[t][1] * SCALE_F + u0.y;
            s[t][2] = s[t][2] * SCALE_F + u1.x;
            s[t][3] = s[t][3] * SCALE_F + u1.y;
            mx0 = fmaxf(mx0, fmaxf(s[t][0], s[t][1]));
            mx1 = fmaxf(mx1, fmaxf(s[t][2], s[t][3]));
        }
        mx0 = fmaxf(mx0, __shfl_xor_sync(0xFFFFFFFFu, mx0, 1));
        mx0 = fmaxf(mx0, __shfl_xor_sync(0xFFFFFFFFu, mx0, 2));
        mx1 = fmaxf(mx1, __shfl_xor_sync(0xFFFFFFFFu, mx1, 1));
        mx1 = fmaxf(mx1, __shfl_xor_sync(0xFFFFFFFFu, mx1, 2));
        const float mn0 = fmaxf(m0v, mx0), mn1 = fmaxf(m1v, mx1);
        const float a0 = __expf(m0v - mn0), a1 = __expf(m1v - mn1);
        m0v = mn0; m1v = mn1;

        float ps0 = 0.f, ps1 = 0.f;
        #pragma unroll
        for (int t = 0; t < 16; t++) {
            s[t][0] = __expf(s[t][0] - mn0);
            s[t][1] = __expf(s[t][1] - mn0);
            s[t][2] = __expf(s[t][2] - mn1);
            s[t][3] = __expf(s[t][3] - mn1);
            ps0 += s[t][0] + s[t][1];
            ps1 += s[t][2] + s[t][3];
        }
        ps0 += __shfl_xor_sync(0xFFFFFFFFu, ps0, 1);
        ps0 += __shfl_xor_sync(0xFFFFFFFFu, ps0, 2);
        ps1 += __shfl_xor_sync(0xFFFFFFFFu, ps1, 1);
        ps1 += __shfl_xor_sync(0xFFFFFFFFu, ps1, 2);
        l0 = l0 * a0 + ps0;
        l1 = l1 * a1 + ps1;

        #pragma unroll
        for (int nt = 0; nt < 8; nt++) {
            o[nt][0] *= a0; o[nt][1] *= a0;
            o[nt][2] *= a1; o[nt][3] *= a1;
        }

        const uint32_t vh = kb + 16384u;
        #pragma unroll
        for (int kt = 0; kt < 8; kt++) {
            uint32_t ph[4];
            ph[0] = pack2h(s[2*kt][0],   s[2*kt][1]);
            ph[1] = pack2h(s[2*kt][2],   s[2*kt][3]);
            ph[2] = pack2h(s[2*kt+1][0], s[2*kt+1][1]);
            ph[3] = pack2h(s[2*kt+1][2], s[2*kt+1][3]);
            #pragma unroll
            for (int nt2 = 0; nt2 < 4; nt2++) {
                int vrow = kt * 16 + (j & 1) * 8 + r;
                int vch  = nt2 * 2 + (j >> 1);
                uint32_t sw = vrow * 128u + ((uint32_t)(vch ^ (vrow & 7)) << 4);
                uint32_t t4[4];
                ldsm4t(t4, vh + sw);
                uint32_t b0[2] = {t4[0], t4[1]}, b1[2] = {t4[2], t4[3]};
                mma16816(o[2*nt2],   ph, b0);
                mma16816(o[2*nt2+1], ph, b1);
            }
        }
        // no trailing barrier (3-stage ring makes it safe)
    }

    const float inv0 = 1.f / l0, inv1 = 1.f / l1;
    const int qrow = b * SS + q0 + wid * 16 + gi;
    #pragma unroll
    for (int nt = 0; nt < 8; nt++) {
        int col = h * DD + nt * 8 + ci * 2;
        *reinterpret_cast<__half2*>(Op + (size_t)qrow * EE + col) =
            __halves2half2(__float2half_rn(o[nt][0] * inv0),
                           __float2half_rn(o[nt][1] * inv0));
        *reinterpret_cast<__half2*>(Op + (size_t)(qrow + 8) * EE + col) =
            __halves2half2(__float2half_rn(o[nt][2] * inv1),
                           __float2half_rn(o[nt][3] * inv1));
    }
}

// ---------------------------------------------------------------------------
// merged E x E transposes: z=0..3 -> wq, wk, wv (into wqkv), wo (into wo_)
// ---------------------------------------------------------------------------
__global__ void transpose_eX4(const float* __restrict__ wq,
                              const float* __restrict__ wk,
                              const float* __restrict__ wv,
                              const float* __restrict__ wo,
                              __half* __restrict__ wqkv,
                              __half* __restrict__ wod) {
    __shared__ float t[32][33];
    int tx = threadIdx.x, ty = threadIdx.y;
    int k0 = blockIdx.y * 32, n0 = blockIdx.x * 32;
    int z = blockIdx.z;
    const float* W = (z == 0) ? wq : (z == 1) ? wk : (z == 2) ? wv : wo;
    __half* dst    = (z == 3) ? wod : wqkv;
    int row_off    = (z == 3) ? 0 : z * EE;
    #pragma unroll
    for (int jj = 0; jj < 4; jj++)
        t[ty + jj*8][tx] = W[(size_t)(k0 + ty + jj*8) * EE + n0 + tx];
    __syncthreads();
    #pragma unroll
    for (int jj = 0; jj < 4; jj++) {
        int nn = row_off + n0 + ty + jj*8;
        int kk = k0 + tx;
        dst[(size_t)nn * EE + kk] = __float2half_rn(t[tx][ty + jj*8]);
    }
}

// plain 1-term transpose: W[K,N] -> wp[N][K] fp16 (for w1, w2)
__global__ void transpose_pack1(const float* __restrict__ W,
                                __half* __restrict__ wp,
                                int K, int N) {
    __shared__ float t[32][33];
    int tx = threadIdx.x, ty = threadIdx.y;
    int k0 = blockIdx.y * 32, n0 = blockIdx.x * 32;
    #pragma unroll
    for (int jj = 0; jj < 4; jj++)
        t[ty + jj*8][tx] = W[(size_t)(k0 + ty + jj*8) * N + n0 + tx];
    __syncthreads();
    #pragma unroll
    for (int jj = 0; jj < 4; jj++) {
        int nn = n0 + ty + jj*8;
        int kk = k0 + tx;
        wp[(size_t)nn * K + kk] = __float2half_rn(t[tx][ty + jj*8]);
    }
}

// ---------------------------------------------------------------------------
__global__ void bias_cat3(const float* __restrict__ bq, const float* __restrict__ bk,
                          const float* __restrict__ bv, float* __restrict__ dst) {
    int i = blockIdx.x * 256 + threadIdx.x;
    if (i < NQKV)
        dst[i] = (i < EE) ? bq[i] : (i < 2*EE) ? bk[i - EE] : bv[i - 2*EE];
}

// ---------------------------------------------------------------------------
__global__ void ln_h(const float* __restrict__ x,
                     const float* __restrict__ g,
                     const float* __restrict__ b,
                     __half* __restrict__ pk) {
    int row = blockIdx.x;
    const float* xr = x + (size_t)row * EE;
    float s = 0.f, s2 = 0.f;
    for (int i = threadIdx.x; i < EE; i += 256) {
        float v = xr[i]; s += v; s2 += v * v;
    }
    __shared__ float rs[8], rs2[8];
    #pragma unroll
    for (int o = 16; o > 0; o >>= 1) {
        s  += __shfl_xor_sync(0xFFFFFFFFu, s,  o);
        s2 += __shfl_xor_sync(0xFFFFFFFFu, s2, o);
    }
    if ((threadIdx.x & 31) == 0) { rs[threadIdx.x>>5] = s; rs2[threadIdx.x>>5] = s2; }
    __syncthreads();
    float ts = 0.f, ts2 = 0.f;
    #pragma unroll
    for (int i = 0; i < 8; i++) { ts += rs[i]; ts2 += rs2[i]; }
    float mean = ts * (1.0f / EE);
    float var  = ts2 * (1.0f / EE) - mean * mean;
    float inv  = rsqrtf(var + EPSF);
    size_t rw = (size_t)row * EE;
    for (int i = threadIdx.x; i < EE; i += 256) {
        float y = (xr[i] - mean) * inv * g[i] + b[i];
        pk[rw + i] = __float2half_rn(y);
    }
}

// ---------------------------------------------------------------------------
extern "C" void kernel_launch(void* const* d_in, const int* in_sizes, int n_in,
                              void* d_out, int out_size) {
    const float* hs   = (const float*)d_in[0];
    const float* mask = (const float*)d_in[1];
    const float* wq   = (const float*)d_in[2];
    const float* bq   = (const float*)d_in[3];
    const float* wk   = (const float*)d_in[4];
    const float* bk   = (const float*)d_in[5];
    const float* wv   = (const float*)d_in[6];
    const float* bv   = (const float*)d_in[7];
    const float* wo   = (const float*)d_in[8];
    const float* bo   = (const float*)d_in[9];
    const float* ln1g = (const float*)d_in[10];
    const float* ln1b = (const float*)d_in[11];
    const float* ln2g = (const float*)d_in[12];
    const float* ln2b = (const float*)d_in[13];
    const float* w1   = (const float*)d_in[14];
    const float* b1   = (const float*)d_in[15];
    const float* w2   = (const float*)d_in[16];
    const float* b2   = (const float*)d_in[17];
    float* out = (float*)d_out;

    float *x, *bqkv;
    __half *h1, *h2, *qkv, *o, *m, *wqkv, *wo_, *w1_, *w2_;
    cudaGetSymbolAddress((void**)&x,    g_x);
    cudaGetSymbolAddress((void**)&bqkv, g_bqkv);
    cudaGetSymbolAddress((void**)&h1,   g_h1);
    cudaGetSymbolAddress((void**)&h2,   g_h2);
    cudaGetSymbolAddress((void**)&qkv,  g_qkv);
    cudaGetSymbolAddress((void**)&o,    g_o);
    cudaGetSymbolAddress((void**)&m,    g_m);
    cudaGetSymbolAddress((void**)&wqkv, g_wqkv);
    cudaGetSymbolAddress((void**)&wo_,  g_wo);
    cudaGetSymbolAddress((void**)&w1_,  g_w1);
    cudaGetSymbolAddress((void**)&w2_,  g_w2);

    cudaFuncSetAttribute(flash_attn, cudaFuncAttributeMaxDynamicSharedMemorySize, FA_SMEM);
    cudaFuncSetAttribute(mma_gemm<0,128>, cudaFuncAttributeMaxDynamicSharedMemorySize, GEMM_SMEM_128);
    cudaFuncSetAttribute(mma_gemm<1,128>, cudaFuncAttributeMaxDynamicSharedMemorySize, GEMM_SMEM_128);
    cudaFuncSetAttribute(mma_gemm<2,64>,  cudaFuncAttributeMaxDynamicSharedMemorySize, GEMM_SMEM_64);

    dim3 tb(32, 8);
    transpose_eX4<<<dim3(EE/32, EE/32, 4), tb>>>(wq, wk, wv, wo, wqkv, wo_);
    transpose_pack1<<<dim3(II/32, EE/32), tb>>>(w1, w1_, EE, II);
    transpose_pack1<<<dim3(EE/32, II/32), tb>>>(w2, w2_, II, EE);
    bias_cat3<<<(NQKV + 255) / 256, 256>>>(bq, bk, bv, bqkv);

    // 1. LN1 -> plain fp16
    ln_h<<<MR, 256>>>(hs, ln1g, ln1b, h1);

    // 2. fused QKV projection (BN=128) -> qkv rows [q|k|v]
    mma_gemm<0,128><<<dim3(NQKV/128, MR/128), 256, GEMM_SMEM_128>>>(
        h1, wqkv, bqkv, nullptr, nullptr, qkv, MR, NQKV, EE, EE, EE, NQKV);

    // 3. fused flash attention -> o (plain fp16)
    flash_attn<<<dim3(SS/128, BB*HH), 256, FA_SMEM>>>(qkv, mask, o);

    // 4. O-proj (BN=64, fixes wave quantization) + residual(hs) -> x
    mma_gemm<2,64><<<dim3(EE/64, MR/128), 256, GEMM_SMEM_64>>>(
        o, wo_, bo, hs, x, nullptr, MR, EE, EE, EE, EE, EE);

    // 5. LN2 -> plain fp16
    ln_h<<<MR, 256>>>(x, ln2g, ln2b, h2);

    // 6. MLP up + gelu (BN=128) -> m (plain fp16)
    mma_gemm<1,128><<<dim3(II/128, MR/128), 256, GEMM_SMEM_128>>>(
        h2, w1_, b1, nullptr, nullptr, m, MR, II, EE, EE, EE, II);

    // 7. MLP down (BN=64, fixes wave quantization) + residual(x) -> out
    mma_gemm<2,64><<<dim3(EE/64, MR/128), 256, GEMM_SMEM_64>>>(
        m, w2_, b2, x, out, nullptr, MR, EE, II, II, II, EE);
}